// round 8
// baseline (speedup 1.0000x reference)
#include <cuda_runtime.h>
#include <cuda_fp16.h>

// ---------------------------------------------------------------------------
// SubdivideMeshes: batched GCN (3 layers) + edge-midpoint subdivision.
// B=16, V=100000, E=300000, Fsub=800000, H=16.
// Feature layout [v][j][b] (j = feature chunk, b = batch lane) in fp16:
//  - each LDG.128 per half-warp covers 256B contiguous (lane stride 16B)
//  - one 512B block per (vertex, edge) serves all 16 batches
// Output (float32): [B, V+E, 3] new_verts then [B, Fsub, 3] faces.
// k_agg_gemm16 is kept at launch slot 4 (the ncu-profiled slot).
// ---------------------------------------------------------------------------

constexpr int   B_    = 16;
constexpr int   V_    = 100000;
constexpr int   E_    = 300000;
constexpr int   FSUB  = 800000;
constexpr int   ROWS  = V_ + E_;
constexpr int   VOUT  = B_ * ROWS * 3;
constexpr float NEG   = 0.01f;
constexpr int   W_ELL = 32;

// Scratch (device globals; allocation-free per harness rules)
__device__ uint4  g_tA[V_ * 32];     // fp16 [v][j2][b]: v*32 + j2*16 + b (51.2 MB)
__device__ uint4  g_tB[V_ * 32];     // 51.2 MB
__device__ float4 g_tC[V_ * 16];     // [v][b] tt3 xyz (25.6 MB)
__device__ float4 g_tD[V_ * 16];     // [v][b] final positions
__device__ float4 g_tX[V_ * 16];     // [v][b] input positions
__device__ int    g_ell[V_ * W_ELL];
__device__ int    g_deg[V_];         // zero-init; reset by k_final each replay

// unpack 8 halves from a uint4 and accumulate into acc[0..7]
__device__ __forceinline__ void acc8(float* acc, uint4 u) {
    const __half2* h = (const __half2*)&u;
#pragma unroll
    for (int k = 0; k < 4; k++) {
        float2 f = __half22float2(h[k]);
        acc[2 * k]     += f.x;
        acc[2 * k + 1] += f.y;
    }
}

__device__ __forceinline__ uint4 pack8(const float* o) {
    uint4 u;
    __half2* h = (__half2*)&u;
#pragma unroll
    for (int k = 0; k < 4; k++) h[k] = __floats2half2_rn(o[2 * k], o[2 * k + 1]);
    return u;
}

// ---------------- ELL build ----------------

__global__ void k_ell(const int* __restrict__ edges) {
    int e = blockIdx.x * blockDim.x + threadIdx.x;
    if (e >= E_) return;
    int2 sd = ((const int2*)edges)[e];
    int slot = atomicAdd(&g_deg[sd.y], 1);
    if (slot < W_ELL) g_ell[sd.y * W_ELL + slot] = sd.x;
}

// ---------------- Layer 1: tt1 = (x @ W1) * dinv, fp16 pack ----------------
// Warp = 2 vertices; lane l -> (v = 2w + (l>>4), b = l&15).

__global__ void k_l1(const float* __restrict__ verts, const float* __restrict__ W1) {
    __shared__ float sW[48];
    if (threadIdx.x < 48) sW[threadIdx.x] = W1[threadIdx.x];
    __syncthreads();
    int warp = (blockIdx.x * blockDim.x + threadIdx.x) >> 5;
    int lane = threadIdx.x & 31;
    int v = 2 * warp + (lane >> 4);
    if (v >= V_) return;
    int b = lane & 15;
    float dv = rsqrtf((float)(g_deg[v] + 1));
    const float* xp = verts + ((size_t)b * V_ + v) * 3;
    float x0 = xp[0], x1 = xp[1], x2 = xp[2];
    g_tX[(size_t)v * 16 + b] = make_float4(x0, x1, x2, 0.f);
    float o[16];
#pragma unroll
    for (int j = 0; j < 16; j++)
        o[j] = (x0 * sW[j] + x1 * sW[16 + j] + x2 * sW[32 + j]) * dv;
    g_tA[(size_t)v * 32 + b]      = pack8(o);
    g_tA[(size_t)v * 32 + 16 + b] = pack8(o + 8);
}

// ---- Fused AGG + GEMM (16->16), fp16 in/out, fp32 accumulate ----

__global__ void k_agg_gemm16(const uint4* __restrict__ tin, uint4* __restrict__ tout,
                             const float* __restrict__ W, const float* __restrict__ bias) {
    __shared__ float sW[256];
    __shared__ float sB[16];
    int t = threadIdx.x;
    if (t < 256) sW[t] = W[t];
    if (t < 16)  sB[t] = bias[t];
    __syncthreads();
    int warp = (blockIdx.x * blockDim.x + t) >> 5;
    int lane = t & 31;
    int v = 2 * warp + (lane >> 4);
    if (v >= V_) return;
    int b = lane & 15;
    int dg = g_deg[v];
    float dv = rsqrtf((float)(dg + 1));
    const int* row = &g_ell[v * W_ELL];
    int idx0 = row[b];
    int idx1 = row[b + 16];
    float acc[16];
#pragma unroll
    for (int j = 0; j < 16; j++) acc[j] = 0.f;
    acc8(acc,     tin[(size_t)v * 32 + b]);
    acc8(acc + 8, tin[(size_t)v * 32 + 16 + b]);
    int dgmax = __reduce_max_sync(0xffffffffu, dg);
    for (int i = 0; i < dgmax; i += 2) {
        int sel0 = (i < 16) ? idx0 : idx1;
        int s0 = __shfl_sync(0xffffffffu, sel0, i & 15, 16);
        int sel1 = ((i + 1) < 16) ? idx0 : idx1;
        int s1 = __shfl_sync(0xffffffffu, sel1, (i + 1) & 15, 16);
        bool p0 = i < dg, p1 = (i + 1) < dg;
        uint4 u0a = {0,0,0,0}, u0b = {0,0,0,0}, u1a = {0,0,0,0}, u1b = {0,0,0,0};
        if (p0) { u0a = tin[(size_t)s0 * 32 + b]; u0b = tin[(size_t)s0 * 32 + 16 + b]; }
        if (p1) { u1a = tin[(size_t)s1 * 32 + b]; u1b = tin[(size_t)s1 * 32 + 16 + b]; }
        if (p0) { acc8(acc, u0a); acc8(acc + 8, u0b); }
        if (p1) { acc8(acc, u1a); acc8(acc + 8, u1b); }
    }
#pragma unroll
    for (int k = 0; k < 16; k++) {
        float x = sB[k] + dv * acc[k];
        acc[k] = (x > 0.f) ? x : NEG * x;
    }
    float o[16];
#pragma unroll
    for (int j = 0; j < 16; j++) o[j] = 0.f;
#pragma unroll
    for (int k = 0; k < 16; k++) {
        float hk = acc[k];
#pragma unroll
        for (int j = 0; j < 16; j++) o[j] += hk * sW[k * 16 + j];
    }
#pragma unroll
    for (int j = 0; j < 16; j++) o[j] *= dv;
    tout[(size_t)v * 32 + b]      = pack8(o);
    tout[(size_t)v * 32 + 16 + b] = pack8(o + 8);
}

// ---- Fused AGG(layer2) + GEMM3 (16->3) -> g_tC[v][b] ----

__global__ void k_agg_gemm3(const float* __restrict__ W3, const float* __restrict__ b2) {
    __shared__ float sW[48];
    __shared__ float sB[16];
    int t = threadIdx.x;
    if (t < 48) sW[t] = W3[t];
    if (t < 16) sB[t] = b2[t];
    __syncthreads();
    int warp = (blockIdx.x * blockDim.x + t) >> 5;
    int lane = t & 31;
    int v = 2 * warp + (lane >> 4);
    if (v >= V_) return;
    int b = lane & 15;
    int dg = g_deg[v];
    float dv = rsqrtf((float)(dg + 1));
    const int* row = &g_ell[v * W_ELL];
    int idx0 = row[b];
    int idx1 = row[b + 16];
    const uint4* __restrict__ tin = g_tB;
    float acc[16];
#pragma unroll
    for (int j = 0; j < 16; j++) acc[j] = 0.f;
    acc8(acc,     tin[(size_t)v * 32 + b]);
    acc8(acc + 8, tin[(size_t)v * 32 + 16 + b]);
    int dgmax = __reduce_max_sync(0xffffffffu, dg);
    for (int i = 0; i < dgmax; i += 2) {
        int sel0 = (i < 16) ? idx0 : idx1;
        int s0 = __shfl_sync(0xffffffffu, sel0, i & 15, 16);
        int sel1 = ((i + 1) < 16) ? idx0 : idx1;
        int s1 = __shfl_sync(0xffffffffu, sel1, (i + 1) & 15, 16);
        bool p0 = i < dg, p1 = (i + 1) < dg;
        uint4 u0a = {0,0,0,0}, u0b = {0,0,0,0}, u1a = {0,0,0,0}, u1b = {0,0,0,0};
        if (p0) { u0a = tin[(size_t)s0 * 32 + b]; u0b = tin[(size_t)s0 * 32 + 16 + b]; }
        if (p1) { u1a = tin[(size_t)s1 * 32 + b]; u1b = tin[(size_t)s1 * 32 + 16 + b]; }
        if (p0) { acc8(acc, u0a); acc8(acc + 8, u0b); }
        if (p1) { acc8(acc, u1a); acc8(acc + 8, u1b); }
    }
#pragma unroll
    for (int k = 0; k < 16; k++) {
        float x = sB[k] + dv * acc[k];
        acc[k] = (x > 0.f) ? x : NEG * x;
    }
    float o0 = 0.f, o1 = 0.f, o2 = 0.f;
#pragma unroll
    for (int k = 0; k < 16; k++) {
        o0 += acc[k] * sW[k * 3 + 0];
        o1 += acc[k] * sW[k * 3 + 1];
        o2 += acc[k] * sW[k * 3 + 2];
    }
    g_tC[(size_t)v * 16 + b] = make_float4(o0 * dv, o1 * dv, o2 * dv, 0.f);
}

// ---- Final AGG(layer3) + residual -> g_tD; resets g_deg for replay ----

__global__ void k_final(const float* __restrict__ b3) {
    __shared__ float sB[3];
    if (threadIdx.x < 3) sB[threadIdx.x] = b3[threadIdx.x];
    __syncthreads();
    int warp = (blockIdx.x * blockDim.x + threadIdx.x) >> 5;
    int lane = threadIdx.x & 31;
    int v = 2 * warp + (lane >> 4);
    if (v >= V_) return;
    int b = lane & 15;
    int dg = g_deg[v];
    float dv = rsqrtf((float)(dg + 1));
    const int* rowp = &g_ell[v * W_ELL];
    int idx0 = rowp[b];
    int idx1 = rowp[b + 16];
    float4 a = g_tC[(size_t)v * 16 + b];
    int dgmax = __reduce_max_sync(0xffffffffu, dg);
    for (int i = 0; i < dgmax; i += 2) {
        int sel0 = (i < 16) ? idx0 : idx1;
        int s0 = __shfl_sync(0xffffffffu, sel0, i & 15, 16);
        int sel1 = ((i + 1) < 16) ? idx0 : idx1;
        int s1 = __shfl_sync(0xffffffffu, sel1, (i + 1) & 15, 16);
        bool p0 = i < dg, p1 = (i + 1) < dg;
        float4 r0 = {0,0,0,0}, r1 = {0,0,0,0};
        if (p0) r0 = g_tC[(size_t)s0 * 16 + b];
        if (p1) r1 = g_tC[(size_t)s1 * 16 + b];
        if (p0) { a.x += r0.x; a.y += r0.y; a.z += r0.z; }
        if (p1) { a.x += r1.x; a.y += r1.y; a.z += r1.z; }
    }
    float4 x = g_tX[(size_t)v * 16 + b];
    float r0 = x.x + sB[0] + dv * a.x;
    float r1 = x.y + sB[1] + dv * a.y;
    float r2 = x.z + sB[2] + dv * a.z;
    g_tD[(size_t)v * 16 + b] = make_float4(r0, r1, r2, 0.f);
    if (b == 0) g_deg[v] = 0;   // replay idempotence
}

// ---- Transpose-out: verts region, coalesced writes ----

__global__ void k_out(float* __restrict__ out) {
    int idx = blockIdx.x * blockDim.x + threadIdx.x;
    if (idx >= B_ * V_) return;
    int b = idx / V_, v = idx - b * V_;
    float4 p = g_tD[(size_t)v * 16 + b];
    size_t o = ((size_t)b * ROWS + v) * 3;
    out[o + 0] = p.x;
    out[o + 1] = p.y;
    out[o + 2] = p.z;
}

// ---- Edge midpoints: coalesced writes, L2-resident reads ----

__global__ void k_mid(const int* __restrict__ edges, float* __restrict__ out) {
    int idx = blockIdx.x * blockDim.x + threadIdx.x;
    if (idx >= B_ * E_) return;
    int b = idx / E_, e = idx - b * E_;
    int2 sd = ((const int2*)edges)[e];
    float4 p = g_tD[(size_t)sd.x * 16 + b];
    float4 q = g_tD[(size_t)sd.y * 16 + b];
    size_t o = ((size_t)b * ROWS + V_ + e) * 3;
    out[o + 0] = 0.5f * (p.x + q.x);
    out[o + 1] = 0.5f * (p.y + q.y);
    out[o + 2] = 0.5f * (p.z + q.z);
}

// ---- Faces broadcast (int -> float), vectorized ----

__global__ void k_faces(const int* __restrict__ faces, float* __restrict__ out) {
    constexpr int Q = FSUB * 3 / 4;
    int i = blockIdx.x * blockDim.x + threadIdx.x;
    if (i >= Q) return;
    int b = blockIdx.y;
    int4 f = ((const int4*)faces)[i];
    float4 w = make_float4((float)f.x, (float)f.y, (float)f.z, (float)f.w);
    ((float4*)(out + VOUT))[(size_t)b * Q + i] = w;
}

// ---------------------------------------------------------------------------

extern "C" void kernel_launch(void* const* d_in, const int* in_sizes, int n_in,
                              void* d_out, int out_size) {
    const float* verts = (const float*)d_in[0];
    const int*   edges = (const int*)d_in[1];
    const int*   faces = (const int*)d_in[2];
    const float* W1 = (const float*)d_in[3];
    const float* b1 = (const float*)d_in[4];
    const float* W2 = (const float*)d_in[5];
    const float* b2 = (const float*)d_in[6];
    const float* W3 = (const float*)d_in[7];
    const float* b3 = (const float*)d_in[8];
    float* out = (float*)d_out;

    int nwarp_v = (V_ + 1) / 2;
    int nb_v = (nwarp_v * 32 + 255) / 256;

    // 1: faces
    dim3 fgrid((FSUB * 3 / 4 + 255) / 256, B_);
    k_faces<<<fgrid, 256>>>(faces, out);
    // 2: ELL adjacency
    k_ell<<<(E_ + 255) / 256, 256>>>(edges);
    // 3: layer-1 GEMM (also caches positions to g_tX)
    k_l1<<<nb_v, 256>>>(verts, W1);
    // 4: AGG1 + GEMM2  <-- ncu-profiled slot
    k_agg_gemm16<<<nb_v, 256>>>(g_tA, g_tB, W2, b1);
    // 5: AGG2 + GEMM3
    k_agg_gemm3<<<nb_v, 256>>>(W3, b2);
    // 6: AGG3 + residual -> g_tD
    k_final<<<nb_v, 256>>>(b3);
    // 7: verts region of out
    k_out<<<(B_ * V_ + 255) / 256, 256>>>(out);
    // 8: midpoints
    k_mid<<<(B_ * E_ + 255) / 256, 256>>>(edges, out);
}